// round 11
// baseline (speedup 1.0000x reference)
#include <cuda_runtime.h>

// IDWT1D Haar inverse, algebraically reduced (R0 analysis) to a streaming
// elementwise map at identical linear offsets:
//   out[2k]   = a_k*lo1 + d_k*hi1
//   out[2k+1] = a_k*lo0 + d_k*hi0
// with (a_k, d_k) packed at input offset 2k. Pure float4 stream, zero reuse.
//
// SESSION-FINAL (R4/R7 config; best measured 74.0us kernel / 81.95us bench).
// Exhaustive axis search results (kernel time):
//   MLP/thread: 2=75.4, 4=74.0-75.6 (BEST), 8=75.7
//   stores: __stcs (BEST), __stwt=74.7, launch: one-shot (BEST),
//   persistent grid-stride=82.9 (software loop collapses MLP at iteration
//   boundaries; CLC block dispatch pipelines wave transitions for free),
//   block: 256 (BEST single run) vs 512=75.3 (equal).
// All configs pin ~6.9 TB/s combined L2-side traffic = B300 LTS fabric cap
// (path-independent); DRAM 80-82% of 8TB/s spec = read+write-mix HBM
// ceiling. issue=10%, fma=5%: nothing else binds. Roofline reached.

__global__ void __launch_bounds__(256)
idwt_haar_kernel(const float4* __restrict__ in, float4* __restrict__ out,
                 const float* __restrict__ lo, const float* __restrict__ hi,
                 long long n4)
{
    const float lo0 = __ldg(lo + 0);
    const float lo1 = __ldg(lo + 1);
    const float hi0 = __ldg(hi + 0);
    const float hi1 = __ldg(hi + 1);

    const int T = 256;
    long long base = (long long)blockIdx.x * (4 * T) + threadIdx.x;

    if (base + 3LL * T < n4) {
        // Front-batched loads (MLP=4), compute, back-batched stores.
        float4 v0 = __ldcs(in + base);
        float4 v1 = __ldcs(in + base + T);
        float4 v2 = __ldcs(in + base + 2 * T);
        float4 v3 = __ldcs(in + base + 3 * T);

        float4 r0, r1, r2, r3;
        r0.x = v0.x * lo1 + v0.y * hi1;  r0.y = v0.x * lo0 + v0.y * hi0;
        r0.z = v0.z * lo1 + v0.w * hi1;  r0.w = v0.z * lo0 + v0.w * hi0;

        r1.x = v1.x * lo1 + v1.y * hi1;  r1.y = v1.x * lo0 + v1.y * hi0;
        r1.z = v1.z * lo1 + v1.w * hi1;  r1.w = v1.z * lo0 + v1.w * hi0;

        r2.x = v2.x * lo1 + v2.y * hi1;  r2.y = v2.x * lo0 + v2.y * hi0;
        r2.z = v2.z * lo1 + v2.w * hi1;  r2.w = v2.z * lo0 + v2.w * hi0;

        r3.x = v3.x * lo1 + v3.y * hi1;  r3.y = v3.x * lo0 + v3.y * hi0;
        r3.z = v3.z * lo1 + v3.w * hi1;  r3.w = v3.z * lo0 + v3.w * hi0;

        __stcs(out + base,         r0);
        __stcs(out + base + T,     r1);
        __stcs(out + base + 2 * T, r2);
        __stcs(out + base + 3 * T, r3);
    } else {
        // Tail (not taken for bench shape: n4 = 2^24, divisible by 1024).
        #pragma unroll
        for (int k = 0; k < 4; k++) {
            long long i = base + (long long)k * T;
            if (i < n4) {
                float4 v = __ldcs(in + i);
                float4 r;
                r.x = v.x * lo1 + v.y * hi1;  r.y = v.x * lo0 + v.y * hi0;
                r.z = v.z * lo1 + v.w * hi1;  r.w = v.z * lo0 + v.w * hi0;
                __stcs(out + i, r);
            }
        }
    }
}

extern "C" void kernel_launch(void* const* d_in, const int* in_sizes, int n_in,
                              void* d_out, int out_size)
{
    const float* x  = (const float*)d_in[0];
    const float* lo = (const float*)d_in[1];
    const float* hi = (const float*)d_in[2];
    float* out = (float*)d_out;

    long long n_floats = (long long)in_sizes[0];
    long long n4 = n_floats / 4;

    const int threads = 256;
    const long long per_block = 4LL * threads;   // 4 float4 per thread
    int blocks = (int)((n4 + per_block - 1) / per_block);

    idwt_haar_kernel<<<blocks, threads>>>((const float4*)x, (float4*)out,
                                          lo, hi, n4);
}

// round 12
// speedup vs baseline: 1.0008x; 1.0008x over previous
#include <cuda_runtime.h>

// IDWT1D Haar inverse, algebraically reduced (R0 analysis) to a streaming
// elementwise map at identical linear offsets:
//   out[2k]   = a_k*lo1 + d_k*hi1
//   out[2k+1] = a_k*lo0 + d_k*hi0
// with (a_k, d_k) packed at input offset 2k. Pure float4 stream, zero reuse.
//
// SESSION-FINAL (reproduced best: 73.9us kernel / 82.0us bench, DRAM 82.3%).
// Exhaustive axis search results (kernel time):
//   MLP/thread: 2=75.4, 4=73.9-75.6 (BEST), 8=75.7
//   stores: __stcs (BEST), __stwt=74.7
//   launch: one-shot 16384 blocks (BEST); persistent grid-stride=82.9
//     (software loop collapses MLP at iteration boundaries; CLC block
//     dispatch pipelines wave transitions for free)
//   block: 256 (BEST) vs 512=75.3 (equal)
// All configs pin ~6.9 TB/s combined L2-side traffic = B300 LTS fabric cap
// (path-independent per B300_MICROARCH); DRAM 80-82% of 8TB/s spec is the
// read+write-mix HBM ceiling. issue=10%, fma=5%: nothing else binds.
// Traffic is irreducible (output = rescaled permutation of input).

__global__ void __launch_bounds__(256)
idwt_haar_kernel(const float4* __restrict__ in, float4* __restrict__ out,
                 const float* __restrict__ lo, const float* __restrict__ hi,
                 long long n4)
{
    const float lo0 = __ldg(lo + 0);
    const float lo1 = __ldg(lo + 1);
    const float hi0 = __ldg(hi + 0);
    const float hi1 = __ldg(hi + 1);

    const int T = 256;
    long long base = (long long)blockIdx.x * (4 * T) + threadIdx.x;

    if (base + 3LL * T < n4) {
        // Front-batched loads (MLP=4), compute, back-batched stores.
        float4 v0 = __ldcs(in + base);
        float4 v1 = __ldcs(in + base + T);
        float4 v2 = __ldcs(in + base + 2 * T);
        float4 v3 = __ldcs(in + base + 3 * T);

        float4 r0, r1, r2, r3;
        r0.x = v0.x * lo1 + v0.y * hi1;  r0.y = v0.x * lo0 + v0.y * hi0;
        r0.z = v0.z * lo1 + v0.w * hi1;  r0.w = v0.z * lo0 + v0.w * hi0;

        r1.x = v1.x * lo1 + v1.y * hi1;  r1.y = v1.x * lo0 + v1.y * hi0;
        r1.z = v1.z * lo1 + v1.w * hi1;  r1.w = v1.z * lo0 + v1.w * hi0;

        r2.x = v2.x * lo1 + v2.y * hi1;  r2.y = v2.x * lo0 + v2.y * hi0;
        r2.z = v2.z * lo1 + v2.w * hi1;  r2.w = v2.z * lo0 + v2.w * hi0;

        r3.x = v3.x * lo1 + v3.y * hi1;  r3.y = v3.x * lo0 + v3.y * hi0;
        r3.z = v3.z * lo1 + v3.w * hi1;  r3.w = v3.z * lo0 + v3.w * hi0;

        __stcs(out + base,         r0);
        __stcs(out + base + T,     r1);
        __stcs(out + base + 2 * T, r2);
        __stcs(out + base + 3 * T, r3);
    } else {
        // Tail (not taken for bench shape: n4 = 2^24, divisible by 1024).
        #pragma unroll
        for (int k = 0; k < 4; k++) {
            long long i = base + (long long)k * T;
            if (i < n4) {
                float4 v = __ldcs(in + i);
                float4 r;
                r.x = v.x * lo1 + v.y * hi1;  r.y = v.x * lo0 + v.y * hi0;
                r.z = v.z * lo1 + v.w * hi1;  r.w = v.z * lo0 + v.w * hi0;
                __stcs(out + i, r);
            }
        }
    }
}

extern "C" void kernel_launch(void* const* d_in, const int* in_sizes, int n_in,
                              void* d_out, int out_size)
{
    const float* x  = (const float*)d_in[0];
    const float* lo = (const float*)d_in[1];
    const float* hi = (const float*)d_in[2];
    float* out = (float*)d_out;

    long long n_floats = (long long)in_sizes[0];
    long long n4 = n_floats / 4;

    const int threads = 256;
    const long long per_block = 4LL * threads;   // 4 float4 per thread
    int blocks = (int)((n4 + per_block - 1) / per_block);

    idwt_haar_kernel<<<blocks, threads>>>((const float4*)x, (float4*)out,
                                          lo, hi, n4);
}

// round 13
// speedup vs baseline: 1.0012x; 1.0004x over previous
#include <cuda_runtime.h>

// IDWT1D Haar inverse, algebraically reduced (R0 analysis) to a streaming
// elementwise map at identical linear offsets:
//   out[2k]   = a_k*lo1 + d_k*hi1
//   out[2k+1] = a_k*lo0 + d_k*hi0
// with (a_k, d_k) packed at input offset 2k. Pure float4 stream, zero reuse.
//
// SESSION-FINAL (stable across 4 runs: 73.9-75.6us kernel, 82.0+-0.4us
// bench, DRAM 80-82%). Exhaustive axis search results (kernel time):
//   MLP/thread: 2=75.4, 4=73.9-75.6 (BEST), 8=75.7
//   stores: __stcs (BEST), __stwt=74.7
//   launch: one-shot 16384 blocks (BEST); persistent grid-stride=82.9
//     (software loop collapses MLP at iteration boundaries; CLC block
//     dispatch pipelines wave transitions for free)
//   block: 256 (BEST) vs 512=75.3 (equal)
// All configs pin ~6.9 TB/s combined L2-side traffic = B300 LTS fabric cap
// (path-independent per B300_MICROARCH); DRAM 80-82% of 8TB/s spec is the
// read+write-mix HBM ceiling. issue=10%, fma=5%: nothing else binds.
// Traffic is irreducible (output = rescaled permutation of input).

__global__ void __launch_bounds__(256)
idwt_haar_kernel(const float4* __restrict__ in, float4* __restrict__ out,
                 const float* __restrict__ lo, const float* __restrict__ hi,
                 long long n4)
{
    const float lo0 = __ldg(lo + 0);
    const float lo1 = __ldg(lo + 1);
    const float hi0 = __ldg(hi + 0);
    const float hi1 = __ldg(hi + 1);

    const int T = 256;
    long long base = (long long)blockIdx.x * (4 * T) + threadIdx.x;

    if (base + 3LL * T < n4) {
        // Front-batched loads (MLP=4), compute, back-batched stores.
        float4 v0 = __ldcs(in + base);
        float4 v1 = __ldcs(in + base + T);
        float4 v2 = __ldcs(in + base + 2 * T);
        float4 v3 = __ldcs(in + base + 3 * T);

        float4 r0, r1, r2, r3;
        r0.x = v0.x * lo1 + v0.y * hi1;  r0.y = v0.x * lo0 + v0.y * hi0;
        r0.z = v0.z * lo1 + v0.w * hi1;  r0.w = v0.z * lo0 + v0.w * hi0;

        r1.x = v1.x * lo1 + v1.y * hi1;  r1.y = v1.x * lo0 + v1.y * hi0;
        r1.z = v1.z * lo1 + v1.w * hi1;  r1.w = v1.z * lo0 + v1.w * hi0;

        r2.x = v2.x * lo1 + v2.y * hi1;  r2.y = v2.x * lo0 + v2.y * hi0;
        r2.z = v2.z * lo1 + v2.w * hi1;  r2.w = v2.z * lo0 + v2.w * hi0;

        r3.x = v3.x * lo1 + v3.y * hi1;  r3.y = v3.x * lo0 + v3.y * hi0;
        r3.z = v3.z * lo1 + v3.w * hi1;  r3.w = v3.z * lo0 + v3.w * hi0;

        __stcs(out + base,         r0);
        __stcs(out + base + T,     r1);
        __stcs(out + base + 2 * T, r2);
        __stcs(out + base + 3 * T, r3);
    } else {
        // Tail (not taken for bench shape: n4 = 2^24, divisible by 1024).
        #pragma unroll
        for (int k = 0; k < 4; k++) {
            long long i = base + (long long)k * T;
            if (i < n4) {
                float4 v = __ldcs(in + i);
                float4 r;
                r.x = v.x * lo1 + v.y * hi1;  r.y = v.x * lo0 + v.y * hi0;
                r.z = v.z * lo1 + v.w * hi1;  r.w = v.z * lo0 + v.w * hi0;
                __stcs(out + i, r);
            }
        }
    }
}

extern "C" void kernel_launch(void* const* d_in, const int* in_sizes, int n_in,
                              void* d_out, int out_size)
{
    const float* x  = (const float*)d_in[0];
    const float* lo = (const float*)d_in[1];
    const float* hi = (const float*)d_in[2];
    float* out = (float*)d_out;

    long long n_floats = (long long)in_sizes[0];
    long long n4 = n_floats / 4;

    const int threads = 256;
    const long long per_block = 4LL * threads;   // 4 float4 per thread
    int blocks = (int)((n4 + per_block - 1) / per_block);

    idwt_haar_kernel<<<blocks, threads>>>((const float4*)x, (float4*)out,
                                          lo, hi, n4);
}